// round 16
// baseline (speedup 1.0000x reference)
#include <cuda_runtime.h>
#include <math.h>

#define BB 32
#define SS 4096
#define DD 512          // INDIM == OUTDIM == 512
#define NCH 32
#define CS (SS / NCH)   // 128 keys per chunk

// ---- scratch (no allocations allowed) ----
__device__ float g_ht[BB * DD];
__device__ float g_scores[BB * SS];
__device__ float g_pm[BB * NCH];
__device__ float g_ps[BB * NCH];
__device__ float g_pc[BB * NCH * DD];
__device__ float g_cfin[BB * DD];

__device__ __forceinline__ int get_len(const int* __restrict__ L, int b) {
    return (L[1] == 0) ? L[2 * b] : L[b];
}

__device__ __forceinline__ float warp_allreduce_sum(float v) {
#pragma unroll
    for (int off = 16; off > 0; off >>= 1)
        v += __shfl_xor_sync(0xffffffffu, v, off);
    return v;
}

// dummies: keep k_attn in ncu's captured launch slot (#4)
__global__ void k_dummy1() {}
__global__ void k_dummy2() {}

// ---------------------------------------------------------------------------
// Kernel 1: h_t = source @ W_in^T  (R8 config)
// ---------------------------------------------------------------------------
__global__ void __launch_bounds__(256, 4) k_ht(const float* __restrict__ src,
                                               const float* __restrict__ Win) {
    int wid = threadIdx.x >> 5, lane = threadIdx.x & 31;
    int o = blockIdx.x * 8 + wid;
    int b0 = blockIdx.y * 4;

    const float4* w4 = (const float4*)(Win + (size_t)o * DD);
    float4 w[4];
#pragma unroll
    for (int j = 0; j < 4; j++) w[j] = w4[lane + 32 * j];

    float acc[4];
#pragma unroll
    for (int i = 0; i < 4; i++) {
        const float4* x4 = (const float4*)(src + (size_t)(b0 + i) * DD);
        float d = 0.f;
#pragma unroll
        for (int j = 0; j < 4; j++) {
            float4 x = x4[lane + 32 * j];
            d += w[j].x * x.x + w[j].y * x.y + w[j].z * x.z + w[j].w * x.w;
        }
        acc[i] = d;
    }
#pragma unroll
    for (int i = 0; i < 4; i++) {
        float t = warp_allreduce_sum(acc[i]);
        if (lane == i) g_ht[(b0 + i) * DD + o] = t;
    }
}

// ---------------------------------------------------------------------------
// Kernel 2: per-warp-pipelined cp.async online-softmax attention.
// Warp w owns keys {s0+w, s0+w+8, ...} and smem slice sm.k[w][0..2][512].
// Each thread cp.asyncs exactly the 4 float4s it later reads -> completion
// tracked by the thread's own wait_group; NO barriers in the main loop.
// 3-deep buffers: ~2 keys (4 KB) in flight per warp -> 32 KB/block,
// 4 blocks/SM (launch_bounds(256,4), 48 KB smem) -> ~128 KB in flight per SM.
// post-loop state (c, ms) overlays the key buffers inside ONE 48 KB union
// (fits the 0xc000 static-smem limit exactly; valid after wait_all+barrier).
// ---------------------------------------------------------------------------
__global__ void __launch_bounds__(256, 4) k_attn(const float* __restrict__ mb,
                                                 const int* __restrict__ L) {
    __shared__ __align__(16) union {
        float k[8][3][DD];                    // 48 KB: [warp][buf][key row]
        struct { float c[8][DD]; float2 ms[8]; } post;  // 16.06 KB overlay
    } sm;

    int b = blockIdx.y, chunk = blockIdx.x;
    int wid = threadIdx.x >> 5, lane = threadIdx.x & 31;
    int len = get_len(L, b);
    int s0 = chunk * CS;
    int send = min(s0 + CS, len);
    int s = s0 + wid;                       // this warp's first key
    int myn = (send > s) ? ((send - s + 7) >> 3) : 0;   // keys for this warp

    const float4* h4 = (const float4*)(g_ht + b * DD);
    float4 h[4];
#pragma unroll
    for (int j = 0; j < 4; j++) h[j] = h4[lane + 32 * j];

    float m = -INFINITY, ssum = 0.f;
    float4 c[4];
#pragma unroll
    for (int j = 0; j < 4; j++) c[j] = make_float4(0.f, 0.f, 0.f, 0.f);

    const float* bbase = mb + (size_t)b * SS * DD;
    unsigned kbase = (unsigned)__cvta_generic_to_shared(&sm)
                   + (unsigned)(wid * 3 * DD * 4) + (unsigned)(lane * 16);

    // issue key #t of this warp into buffer u; ALWAYS commits one group
    // (empty groups keep per-thread group accounting uniform).
    auto issue_key = [&](int t, int u) {
        if (t < myn) {
            const float4* srcp = (const float4*)(bbase + (size_t)(s + 8 * t) * DD)
                               + lane;
            unsigned dst = kbase + (unsigned)(u * DD * 4);
#pragma unroll
            for (int j = 0; j < 4; j++)
                asm volatile("cp.async.cg.shared.global [%0], [%1], 16;"
                             :: "r"(dst + j * 512u), "l"(srcp + 32 * j));
        }
        asm volatile("cp.async.commit_group;");
    };

    issue_key(0, 0); issue_key(1, 1); issue_key(2, 2);

    int u = 0;                               // rotating buffer index
    for (int t = 0; t < myn; t++) {
        asm volatile("cp.async.wait_group 2;");   // key t resident
        const float4* kp = (const float4*)sm.k[wid][u];
        float4 kv[4];
        float dot = 0.f;
#pragma unroll
        for (int j = 0; j < 4; j++) {
            kv[j] = kp[lane + 32 * j];
            dot += h[j].x * kv[j].x + h[j].y * kv[j].y
                 + h[j].z * kv[j].z + h[j].w * kv[j].w;
        }
        float score = warp_allreduce_sum(dot);
        if (lane == 0) g_scores[b * SS + s + 8 * t] = score;

        float mn = fmaxf(score, m);
        float sc = (m == -INFINITY) ? 0.f : __expf(m - mn);
        float p = __expf(score - mn);
        ssum = ssum * sc + p;
#pragma unroll
        for (int j = 0; j < 4; j++) {
            c[j].x = c[j].x * sc + p * kv[j].x;
            c[j].y = c[j].y * sc + p * kv[j].y;
            c[j].z = c[j].z * sc + p * kv[j].z;
            c[j].w = c[j].w * sc + p * kv[j].w;
        }
        m = mn;
        // refill buffer u with key t+3 (kv fully consumed above -> smem free)
        issue_key(t + 3, u);
        u = (u == 2) ? 0 : u + 1;
    }
    asm volatile("cp.async.wait_all;");      // drain before union reuse
    __syncthreads();

    // block combine (deterministic fixed order)
    if (lane == 0) sm.post.ms[wid] = make_float2(m, ssum);
    __syncthreads();

    float M = -INFINITY;
#pragma unroll
    for (int w = 0; w < 8; w++) M = fmaxf(M, sm.post.ms[w].x);

    float f = (m == -INFINITY) ? 0.f : __expf(m - M);
    float4* cb4 = (float4*)sm.post.c[wid];
#pragma unroll
    for (int j = 0; j < 4; j++) {
        float4 v = c[j];
        v.x *= f; v.y *= f; v.z *= f; v.w *= f;
        cb4[lane + 32 * j] = v;
    }
    __syncthreads();

    int pi = b * NCH + chunk;
    if (threadIdx.x == 0) {
        float Sc = 0.f;
#pragma unroll
        for (int w = 0; w < 8; w++) {
            float fm = sm.post.ms[w].x;
            float fw = (fm == -INFINITY) ? 0.f : __expf(fm - M);
            Sc += sm.post.ms[w].y * fw;
        }
        g_pm[pi] = M;
        g_ps[pi] = Sc;
    }
    for (int d = threadIdx.x; d < DD; d += 256) {
        float acc = 0.f;
#pragma unroll
        for (int w = 0; w < 8; w++) acc += sm.post.c[w][d];
        g_pc[pi * DD + d] = acc;
    }
}

// ---------------------------------------------------------------------------
// Kernel 3: merge chunk partials; write align_vectors. (R8 config)
// ---------------------------------------------------------------------------
__global__ void __launch_bounds__(256) k_reduce(const int* __restrict__ L,
                                                float* __restrict__ out) {
    int b = blockIdx.x, part = blockIdx.y;
    int len = get_len(L, b);

    float M = -INFINITY;
#pragma unroll
    for (int i = 0; i < NCH; i++) M = fmaxf(M, g_pm[b * NCH + i]);

    float e[NCH];
    float Ssum = 0.f;
#pragma unroll
    for (int i = 0; i < NCH; i++) {
        float mi = g_pm[b * NCH + i];
        e[i] = (mi == -INFINITY) ? 0.f : __expf(mi - M);
        Ssum += g_ps[b * NCH + i] * e[i];
    }
    float invS = 1.f / Ssum;

    if (threadIdx.x < DD / 8) {
        int d = part * (DD / 8) + threadIdx.x;
        float acc = 0.f;
#pragma unroll
        for (int i = 0; i < NCH; i++) acc += g_pc[(b * NCH + i) * DD + d] * e[i];
        g_cfin[b * DD + d] = acc * invS;
    }

    float* ali = out + BB * DD + (size_t)b * SS;
    int sbase = part * (SS / 8);
    for (int t = threadIdx.x; t < SS / 8; t += 256) {
        int sPos = sbase + t;
        ali[sPos] = (sPos < len) ? __expf(g_scores[b * SS + sPos] - M) * invS : 0.f;
    }
}

// ---------------------------------------------------------------------------
// Kernel 4: attn_h = [c_fin|src] @ W_out^T  (R8 config)
// ---------------------------------------------------------------------------
__global__ void __launch_bounds__(256, 4) k_out(const float* __restrict__ src,
                                                const float* __restrict__ Wout,
                                                float* __restrict__ out) {
    int wid = threadIdx.x >> 5, lane = threadIdx.x & 31;
    int o = blockIdx.x * 8 + wid;
    int b0 = blockIdx.y * 4;

    const float4* w4 = (const float4*)(Wout + (size_t)o * (2 * DD));
    float4 w[8];
#pragma unroll
    for (int j = 0; j < 8; j++) w[j] = w4[lane + 32 * j];

    float acc[4];
#pragma unroll
    for (int i = 0; i < 4; i++) {
        int b = b0 + i;
        const float4* c4 = (const float4*)(g_cfin + (size_t)b * DD);
        const float4* s4 = (const float4*)(src + (size_t)b * DD);
        float d = 0.f;
#pragma unroll
        for (int j = 0; j < 4; j++) {
            float4 x = c4[lane + 32 * j];
            d += w[j].x * x.x + w[j].y * x.y + w[j].z * x.z + w[j].w * x.w;
        }
#pragma unroll
        for (int j = 0; j < 4; j++) {
            float4 x = s4[lane + 32 * j];
            d += w[4 + j].x * x.x + w[4 + j].y * x.y
               + w[4 + j].z * x.z + w[4 + j].w * x.w;
        }
        acc[i] = d;
    }
#pragma unroll
    for (int i = 0; i < 4; i++) {
        float t = warp_allreduce_sum(acc[i]);
        if (lane == i) out[(b0 + i) * DD + o] = t;
    }
}

// ---------------------------------------------------------------------------
extern "C" void kernel_launch(void* const* d_in, const int* in_sizes, int n_in,
                              void* d_out, int out_size) {
    const float* src  = (const float*)d_in[0];
    const float* mb   = (const float*)d_in[1];
    const int*   L    = (const int*)  d_in[2];
    const float* Win  = (const float*)d_in[3];
    const float* Wout = (const float*)d_in[4];
    float* out = (float*)d_out;   // [32*512 attn_h | 32*4096 align]

    k_dummy1<<<1, 32>>>();
    k_dummy2<<<1, 32>>>();
    k_ht    <<<dim3(64, 8), 256>>>(src, Win);
    k_attn  <<<dim3(NCH, BB), 256>>>(mb, L);   // launch #4 -> ncu captures this
    k_reduce<<<dim3(BB, 8), 256>>>(L, out);
    k_out   <<<dim3(64, 8), 256>>>(src, Wout, out);
}

// round 17
// speedup vs baseline: 1.0407x; 1.0407x over previous
#include <cuda_runtime.h>
#include <math.h>

#define BB 32
#define SS 4096
#define DD 512          // INDIM == OUTDIM == 512
#define NCH 32
#define CS (SS / NCH)   // 128 keys per chunk

// ---- scratch (no allocations allowed) ----
__device__ float g_ht[BB * DD];
__device__ float g_scores[BB * SS];
__device__ float g_pm[BB * NCH];
__device__ float g_ps[BB * NCH];
__device__ float g_pc[BB * NCH * DD];
__device__ float g_cfin[BB * DD];

__device__ __forceinline__ int get_len(const int* __restrict__ L, int b) {
    return (L[1] == 0) ? L[2 * b] : L[b];
}

__device__ __forceinline__ float warp_allreduce_sum(float v) {
#pragma unroll
    for (int off = 16; off > 0; off >>= 1)
        v += __shfl_xor_sync(0xffffffffu, v, off);
    return v;
}

// ---------------------------------------------------------------------------
// Kernel 1: h_t = source @ W_in^T  (R8 config)
// ---------------------------------------------------------------------------
__global__ void __launch_bounds__(256, 4) k_ht(const float* __restrict__ src,
                                               const float* __restrict__ Win) {
    int wid = threadIdx.x >> 5, lane = threadIdx.x & 31;
    int o = blockIdx.x * 8 + wid;
    int b0 = blockIdx.y * 4;

    const float4* w4 = (const float4*)(Win + (size_t)o * DD);
    float4 w[4];
#pragma unroll
    for (int j = 0; j < 4; j++) w[j] = w4[lane + 32 * j];

    float acc[4];
#pragma unroll
    for (int i = 0; i < 4; i++) {
        const float4* x4 = (const float4*)(src + (size_t)(b0 + i) * DD);
        float d = 0.f;
#pragma unroll
        for (int j = 0; j < 4; j++) {
            float4 x = x4[lane + 32 * j];
            d += w[j].x * x.x + w[j].y * x.y + w[j].z * x.z + w[j].w * x.w;
        }
        acc[i] = d;
    }
#pragma unroll
    for (int i = 0; i < 4; i++) {
        float t = warp_allreduce_sum(acc[i]);
        if (lane == i) g_ht[(b0 + i) * DD + o] = t;
    }
}

// ---------------------------------------------------------------------------
// Kernel 2: single-pass online-softmax attention (R12 LDG version, 39.6us —
// within ~4% of the measured-achievable 5.05 TB/s stream ceiling; frozen).
// ---------------------------------------------------------------------------
__global__ void __launch_bounds__(256) k_attn(const float* __restrict__ mb,
                                              const int* __restrict__ L) {
    __shared__ float  cbuf[8][DD];   // 16 KB: per-warp scaled context
    __shared__ float2 ms[8];         // per-warp (m, sum)

    int b = blockIdx.y, chunk = blockIdx.x;
    int wid = threadIdx.x >> 5, lane = threadIdx.x & 31;
    int len = get_len(L, b);
    int s0 = chunk * CS;
    int send = min(s0 + CS, len);

    const float4* h4 = (const float4*)(g_ht + b * DD);
    float4 h[4];
#pragma unroll
    for (int j = 0; j < 4; j++) h[j] = h4[lane + 32 * j];

    float m = -INFINITY, ssum = 0.f;
    float4 c[4];
#pragma unroll
    for (int j = 0; j < 4; j++) c[j] = make_float4(0.f, 0.f, 0.f, 0.f);

    const float* bbase = mb + (size_t)b * SS * DD;
    int s = s0 + wid;

    for (; s + 8 < send; s += 16) {
        const float4* k4a = (const float4*)(bbase + (size_t)s * DD);
        const float4* k4b = (const float4*)(bbase + (size_t)(s + 8) * DD);
        float4 ka[4], kb[4];
#pragma unroll
        for (int j = 0; j < 4; j++) ka[j] = k4a[lane + 32 * j];
#pragma unroll
        for (int j = 0; j < 4; j++) kb[j] = k4b[lane + 32 * j];

        float da = 0.f, db = 0.f;
#pragma unroll
        for (int j = 0; j < 4; j++) {
            da += h[j].x * ka[j].x + h[j].y * ka[j].y
                + h[j].z * ka[j].z + h[j].w * ka[j].w;
            db += h[j].x * kb[j].x + h[j].y * kb[j].y
                + h[j].z * kb[j].z + h[j].w * kb[j].w;
        }
        float sa = warp_allreduce_sum(da);
        float sb = warp_allreduce_sum(db);
        if (lane == 0) {
            g_scores[b * SS + s]     = sa;
            g_scores[b * SS + s + 8] = sb;
        }

        float mx = fmaxf(sa, sb);
        if (mx <= m) {                       // common path: no rescale
            float pa = __expf(sa - m);
            float pb = __expf(sb - m);
            ssum += pa + pb;
#pragma unroll
            for (int j = 0; j < 4; j++) {
                c[j].x += pa * ka[j].x + pb * kb[j].x;
                c[j].y += pa * ka[j].y + pb * kb[j].y;
                c[j].z += pa * ka[j].z + pb * kb[j].z;
                c[j].w += pa * ka[j].w + pb * kb[j].w;
            }
        } else {                             // new max: rescale accumulators
            float sc = (m == -INFINITY) ? 0.f : __expf(m - mx);
            float pa = __expf(sa - mx);
            float pb = __expf(sb - mx);
            ssum = ssum * sc + pa + pb;
#pragma unroll
            for (int j = 0; j < 4; j++) {
                c[j].x = c[j].x * sc + pa * ka[j].x + pb * kb[j].x;
                c[j].y = c[j].y * sc + pa * ka[j].y + pb * kb[j].y;
                c[j].z = c[j].z * sc + pa * ka[j].z + pb * kb[j].z;
                c[j].w = c[j].w * sc + pa * ka[j].w + pb * kb[j].w;
            }
            m = mx;
        }
    }
    if (s < send) {                          // tail: at most one key per warp
        const float4* k4 = (const float4*)(bbase + (size_t)s * DD);
        float4 kv[4];
        float dot = 0.f;
#pragma unroll
        for (int j = 0; j < 4; j++) {
            kv[j] = k4[lane + 32 * j];
            dot += h[j].x * kv[j].x + h[j].y * kv[j].y
                 + h[j].z * kv[j].z + h[j].w * kv[j].w;
        }
        float score = warp_allreduce_sum(dot);
        if (lane == 0) g_scores[b * SS + s] = score;

        float mn = fmaxf(score, m);
        float sc = (m == -INFINITY) ? 0.f : __expf(m - mn);
        float p = __expf(score - mn);
        ssum = ssum * sc + p;
#pragma unroll
        for (int j = 0; j < 4; j++) {
            c[j].x = c[j].x * sc + p * kv[j].x;
            c[j].y = c[j].y * sc + p * kv[j].y;
            c[j].z = c[j].z * sc + p * kv[j].z;
            c[j].w = c[j].w * sc + p * kv[j].w;
        }
        m = mn;
    }

    if (lane == 0) ms[wid] = make_float2(m, ssum);
    __syncthreads();

    float M = -INFINITY;
#pragma unroll
    for (int w = 0; w < 8; w++) M = fmaxf(M, ms[w].x);

    float f = (m == -INFINITY) ? 0.f : __expf(m - M);
    float4* cb4 = (float4*)cbuf[wid];
#pragma unroll
    for (int j = 0; j < 4; j++) {
        float4 v = c[j];
        v.x *= f; v.y *= f; v.z *= f; v.w *= f;
        cb4[lane + 32 * j] = v;
    }
    __syncthreads();

    int pi = b * NCH + chunk;
    if (threadIdx.x == 0) {
        float Sc = 0.f;
#pragma unroll
        for (int w = 0; w < 8; w++) {
            float fm = ms[w].x;
            float fw = (fm == -INFINITY) ? 0.f : __expf(fm - M);
            Sc += ms[w].y * fw;
        }
        g_pm[pi] = M;
        g_ps[pi] = Sc;
    }
    // deterministic fixed-order cross-warp sum
    for (int d = threadIdx.x; d < DD; d += 256) {
        float acc = 0.f;
#pragma unroll
        for (int w = 0; w < 8; w++) acc += cbuf[w][d];
        g_pc[pi * DD + d] = acc;
    }
}

// ---------------------------------------------------------------------------
// Kernel 3: merge chunk partials; write align_vectors. (R8 config)
// ---------------------------------------------------------------------------
__global__ void __launch_bounds__(256) k_reduce(const int* __restrict__ L,
                                                float* __restrict__ out) {
    int b = blockIdx.x, part = blockIdx.y;
    int len = get_len(L, b);

    float M = -INFINITY;
#pragma unroll
    for (int i = 0; i < NCH; i++) M = fmaxf(M, g_pm[b * NCH + i]);

    float e[NCH];
    float Ssum = 0.f;
#pragma unroll
    for (int i = 0; i < NCH; i++) {
        float mi = g_pm[b * NCH + i];
        e[i] = (mi == -INFINITY) ? 0.f : __expf(mi - M);
        Ssum += g_ps[b * NCH + i] * e[i];
    }
    float invS = 1.f / Ssum;

    if (threadIdx.x < DD / 8) {
        int d = part * (DD / 8) + threadIdx.x;
        float acc = 0.f;
#pragma unroll
        for (int i = 0; i < NCH; i++) acc += g_pc[(b * NCH + i) * DD + d] * e[i];
        g_cfin[b * DD + d] = acc * invS;
    }

    float* ali = out + BB * DD + (size_t)b * SS;
    int sbase = part * (SS / 8);
    for (int t = threadIdx.x; t < SS / 8; t += 256) {
        int sPos = sbase + t;
        ali[sPos] = (sPos < len) ? __expf(g_scores[b * SS + sPos] - M) * invS : 0.f;
    }
}

// ---------------------------------------------------------------------------
// Kernel 4: attn_h = [c_fin|src] @ W_out^T.
// grid (64,8), warp-per-output, W row in 32 regs (loads issued BEFORE the
// staging barrier so their DRAM/L2 latency overlaps). The block's 4 x-vectors
// are staged in smem ONCE (16 KB) -> per-batch x reads become LDS, halving
// the L1tex global-wavefront pressure that bound the 8us version.
// ---------------------------------------------------------------------------
__global__ void __launch_bounds__(256, 4) k_out(const float* __restrict__ src,
                                                const float* __restrict__ Wout,
                                                float* __restrict__ out) {
    __shared__ __align__(16) float xs[4][2 * DD];   // 16 KB: [batch][c|s]
    int wid = threadIdx.x >> 5, lane = threadIdx.x & 31;
    int o = blockIdx.x * 8 + wid;
    int b0 = blockIdx.y * 4;

    // W loads first: long-latency, overlap with staging below
    const float4* w4 = (const float4*)(Wout + (size_t)o * (2 * DD));
    float4 w[8];
#pragma unroll
    for (int j = 0; j < 8; j++) w[j] = w4[lane + 32 * j];

    // stage x: 4 batches x 256 float4 = 1024 float4, 4 per thread
#pragma unroll
    for (int k = 0; k < 4; k++) {
        int i = k * 256 + threadIdx.x;
        int bi = i >> 8, col = i & 255;
        float4 v = (col < 128)
            ? ((const float4*)(g_cfin + (size_t)(b0 + bi) * DD))[col]
            : ((const float4*)(src + (size_t)(b0 + bi) * DD))[col - 128];
        ((float4*)xs[bi])[col] = v;
    }
    __syncthreads();

    float acc[4];
#pragma unroll
    for (int i = 0; i < 4; i++) {
        const float4* xp = (const float4*)xs[i];
        float d = 0.f;
#pragma unroll
        for (int j = 0; j < 8; j++) {
            float4 x = xp[lane + 32 * j];
            d += w[j].x * x.x + w[j].y * x.y + w[j].z * x.z + w[j].w * x.w;
        }
        acc[i] = d;
    }
#pragma unroll
    for (int i = 0; i < 4; i++) {
        float t = warp_allreduce_sum(acc[i]);
        if (lane == i) out[(b0 + i) * DD + o] = t;
    }
}

// ---------------------------------------------------------------------------
extern "C" void kernel_launch(void* const* d_in, const int* in_sizes, int n_in,
                              void* d_out, int out_size) {
    const float* src  = (const float*)d_in[0];
    const float* mb   = (const float*)d_in[1];
    const int*   L    = (const int*)  d_in[2];
    const float* Win  = (const float*)d_in[3];
    const float* Wout = (const float*)d_in[4];
    float* out = (float*)d_out;   // [32*512 attn_h | 32*4096 align]

    k_ht    <<<dim3(64, 8), 256>>>(src, Win);
    k_attn  <<<dim3(NCH, BB), 256>>>(mb, L);
    k_reduce<<<dim3(BB, 8), 256>>>(L, out);
    k_out   <<<dim3(64, 8), 256>>>(src, Wout, out);
}